// round 3
// baseline (speedup 1.0000x reference)
#include <cuda_runtime.h>
#include <stdint.h>

// Problem shape (fixed by dataset): x[B=128, C=3, L=256, L=256] f32,
// X/Y/W/H each [N=4, B=128] int32.
#define BB 128
#define CC 3
#define LL 256
#define NN 4

// One thread handles 16 consecutive float4 (64 floats = quarter of a row).
// Total float4 = 128*3*256*256/4 = 6,291,456 ; threads = /16 = 393,216.
__global__ __launch_bounds__(256) void masking_kernel(
    const float4* __restrict__ x,
    const int* __restrict__ Xb,
    const int* __restrict__ Yb,
    const int* __restrict__ Wb,
    const int* __restrict__ Hb,
    float4* __restrict__ out)
{
    const int tid = blockIdx.x * blockDim.x + threadIdx.x;   // 0 .. 393215
    const int rowId = tid >> 2;        // (b, c, y) row index, 0 .. 98303
    const int chunk = tid & 3;         // which 64-float quarter of the row
    const int y  = rowId & (LL - 1);   // row within image
    const int bc = rowId >> 8;         // b*C + c
    const int b  = bc / CC;

    // Per-box interval for this row: lane x masked iff (unsigned)(x - lo[n]) <= wl[n].
    // Inactive rows get lo = huge so the unsigned compare always fails.
    int lo[NN], wl[NN];
#pragma unroll
    for (int n = 0; n < NN; n++) {
        const int yy = __ldg(&Yb[n * BB + b]);
        const int hh = __ldg(&Hb[n * BB + b]);
        const int xx = __ldg(&Xb[n * BB + b]);
        const int ww = __ldg(&Wb[n * BB + b]);
        const bool act = (y >= yy) && (y <= yy + hh);
        lo[n] = act ? xx : 0x40000000;
        wl[n] = ww;
    }

    const float4* __restrict__ src = x   + (size_t)tid * 16;
    float4*       __restrict__ dst = out + (size_t)tid * 16;
    const int xbase = chunk * 64;

#pragma unroll
    for (int j = 0; j < 16; j++) {
        float4 v = src[j];
        const int x0 = xbase + j * 4;
        float f[4] = {v.x, v.y, v.z, v.w};
#pragma unroll
        for (int k = 0; k < 4; k++) {
            const int xc = x0 + k;
            bool m = false;
#pragma unroll
            for (int n = 0; n < NN; n++) {
                m |= ((unsigned)(xc - lo[n]) <= (unsigned)wl[n]);
            }
            f[k] = m ? 0.0f : f[k];
        }
        v.x = f[0]; v.y = f[1]; v.z = f[2]; v.w = f[3];
        dst[j] = v;
    }
}

extern "C" void kernel_launch(void* const* d_in, const int* in_sizes, int n_in,
                              void* d_out, int out_size)
{
    const float4* x  = (const float4*)d_in[0];
    const int*    Xb = (const int*)d_in[1];
    const int*    Yb = (const int*)d_in[2];
    const int*    Wb = (const int*)d_in[3];
    const int*    Hb = (const int*)d_in[4];
    float4* out = (float4*)d_out;

    const int total_threads = (BB * CC * LL * LL) / 64;  // 393216
    const int block = 256;
    const int grid  = total_threads / block;             // 1536
    masking_kernel<<<grid, block>>>(x, Xb, Yb, Wb, Hb, out);
}

// round 7
// speedup vs baseline: 1.3599x; 1.3599x over previous
#include <cuda_runtime.h>
#include <stdint.h>

// x[B=128, C=3, L=256, L=256] f32 ; X/Y/W/H each [N=4, B=128] int32.
#define BB 128
#define CC 3
#define LL 256
#define NN 4
#define V  8   // float4 per thread, front-batched for MLP

// Thread handles V=8 consecutive float4 (32 floats = 1/8 of a row).
// threads = 128*3*256*256/32 = 786,432 ; grid = 3072 x 256.
__global__ __launch_bounds__(256, 4) void masking_kernel(
    const float4* __restrict__ x,
    const int* __restrict__ Xb,
    const int* __restrict__ Yb,
    const int* __restrict__ Wb,
    const int* __restrict__ Hb,
    float4* __restrict__ out)
{
    const int tid = blockIdx.x * blockDim.x + threadIdx.x;   // 0 .. 786431
    const int rowId = tid >> 3;        // (b, c, y) row index
    const int chunk = tid & 7;         // which 32-float eighth of the row
    const int y  = rowId & (LL - 1);
    const int bc = rowId >> 8;
    const int b  = bc / CC;

    const float4* __restrict__ src = x   + (size_t)tid * V;
    float4*       __restrict__ dst = out + (size_t)tid * V;

    // ---- front-batched loads: all 8 LDG.128 issued before any consumer ----
    float4 v[V];
#pragma unroll
    for (int j = 0; j < V; j++) v[j] = src[j];

    // Per-box interval for this row: lane masked iff (unsigned)(xc - lo) <= wl.
    int lo[NN], wl[NN];
#pragma unroll
    for (int n = 0; n < NN; n++) {
        const int yy = __ldg(&Yb[n * BB + b]);
        const int hh = __ldg(&Hb[n * BB + b]);
        const int xx = __ldg(&Xb[n * BB + b]);
        const int ww = __ldg(&Wb[n * BB + b]);
        const bool act = (y >= yy) && (y <= yy + hh);
        lo[n] = act ? xx : 0x40000000;   // inactive row -> compare always false
        wl[n] = ww;
    }

    const int xbase = chunk * (V * 4);

#pragma unroll
    for (int j = 0; j < V; j++) {
        const int x0 = xbase + j * 4;
        float f[4] = {v[j].x, v[j].y, v[j].z, v[j].w};
#pragma unroll
        for (int k = 0; k < 4; k++) {
            const int xc = x0 + k;
            bool m = false;
#pragma unroll
            for (int n = 0; n < NN; n++)
                m |= ((unsigned)(xc - lo[n]) <= (unsigned)wl[n]);
            f[k] = m ? 0.0f : f[k];
        }
        float4 o; o.x = f[0]; o.y = f[1]; o.z = f[2]; o.w = f[3];
        dst[j] = o;
    }
}

extern "C" void kernel_launch(void* const* d_in, const int* in_sizes, int n_in,
                              void* d_out, int out_size)
{
    const float4* x  = (const float4*)d_in[0];
    const int*    Xb = (const int*)d_in[1];
    const int*    Yb = (const int*)d_in[2];
    const int*    Wb = (const int*)d_in[3];
    const int*    Hb = (const int*)d_in[4];
    float4* out = (float4*)d_out;

    const int total_threads = (BB * CC * LL * LL) / (V * 4);  // 786432
    const int block = 256;
    const int grid  = total_threads / block;                  // 3072
    masking_kernel<<<grid, block>>>(x, Xb, Yb, Wb, Hb, out);
}

// round 8
// speedup vs baseline: 1.8173x; 1.3363x over previous
#include <cuda_runtime.h>
#include <stdint.h>

// x[B=128, C=3, L=256, L=256] f32 ; X/Y/W/H each [N=4, B=128] int32.
#define BB 128
#define CC 3
#define LL 256
#define NN 4

#define STAGES   3
#define TILE_F4  1024          // float4 per tile = 16 KB
#define THREADS  256
#define FPT      4             // float4 per thread per tile (4*16B = 64B)
// total float4 = 128*3*256*256/4 = 6,291,456 ; tiles = 6144

__device__ __forceinline__ void cpasync16(uint32_t smem, const void* gmem) {
    asm volatile("cp.async.cg.shared.global [%0], [%1], 16;" :: "r"(smem), "l"(gmem));
}
__device__ __forceinline__ void cpcommit() {
    asm volatile("cp.async.commit_group;" ::: "memory");
}
template <int N> __device__ __forceinline__ void cpwait() {
    asm volatile("cp.async.wait_group %0;" :: "n"(N) : "memory");
}

__global__ __launch_bounds__(THREADS) void masking_pipe(
    const float4* __restrict__ x,
    const int* __restrict__ Xb, const int* __restrict__ Yb,
    const int* __restrict__ Wb, const int* __restrict__ Hb,
    float4* __restrict__ out, int numTiles)
{
    __shared__ float4 buf[STAGES][TILE_F4];   // 48 KB exactly
    const int tid = threadIdx.x;
    const int G   = gridDim.x;

    // Per-thread smem slot base (this thread's 64B within each stage).
    const uint32_t sb0 = (uint32_t)__cvta_generic_to_shared(&buf[0][tid * FPT]);

    // ---- prefill all STAGES (empty groups still committed -> counts stay aligned)
    #pragma unroll
    for (int s = 0; s < STAGES; s++) {
        const int t = blockIdx.x + s * G;
        if (t < numTiles) {
            const float4* src = x + (size_t)t * TILE_F4 + tid * FPT;
            const uint32_t sb = sb0 + s * (TILE_F4 * 16);
            #pragma unroll
            for (int k = 0; k < FPT; k++)
                cpasync16(sb + k * 16, (const void*)(src + k));
        }
        cpcommit();
    }

    // ---- main loop: barrier-free (each thread consumes only its own copies)
    int s = 0;
    for (int t = blockIdx.x; t < numTiles; t += G) {
        cpwait<STAGES - 1>();                       // oldest group (stage s) done

        const uint32_t sb = sb0 + s * (TILE_F4 * 16);

        // Decode tile -> (b, y, xc0). Tile = 16 full rows of one (b,c) image.
        const int img = t >> 4;                     // 16 tiles per 256x256 image
        const int b   = img / CC;
        const int rem = ((t & 15) << 12) + (tid << 4);  // float offset in image
        const int y   = rem >> 8;
        const int xc0 = rem & (LL - 1);             // 16 consecutive x positions

        // Box intervals for this row; lane masked iff (unsigned)(xc-lo) <= wl.
        int lo[NN], wl[NN];
        #pragma unroll
        for (int n = 0; n < NN; n++) {
            const int yy = __ldg(&Yb[n * BB + b]);
            const int hh = __ldg(&Hb[n * BB + b]);
            const int xx = __ldg(&Xb[n * BB + b]);
            const int ww = __ldg(&Wb[n * BB + b]);
            const bool act = (y >= yy) && (y <= yy + hh);
            lo[n] = act ? xx : 0x40000000;
            wl[n] = ww;
        }

        float4* dst = out + (size_t)t * TILE_F4 + tid * FPT;
        #pragma unroll
        for (int k = 0; k < FPT; k++) {
            float4 v = buf[s][tid * FPT + k];
            const int x0 = xc0 + k * 4;
            float f[4] = {v.x, v.y, v.z, v.w};
            #pragma unroll
            for (int c = 0; c < 4; c++) {
                const int xc = x0 + c;
                bool m = false;
                #pragma unroll
                for (int n = 0; n < NN; n++)
                    m |= ((unsigned)(xc - lo[n]) <= (unsigned)wl[n]);
                f[c] = m ? 0.0f : f[c];
            }
            float4 o; o.x = f[0]; o.y = f[1]; o.z = f[2]; o.w = f[3];
            dst[k] = o;
        }

        // Refill this stage with tile t + STAGES*G (skip if OOB, still commit).
        const int tn = t + STAGES * G;
        if (tn < numTiles) {
            const float4* src = x + (size_t)tn * TILE_F4 + tid * FPT;
            #pragma unroll
            for (int k = 0; k < FPT; k++)
                cpasync16(sb + k * 16, (const void*)(src + k));
        }
        cpcommit();

        if (++s == STAGES) s = 0;
    }
}

extern "C" void kernel_launch(void* const* d_in, const int* in_sizes, int n_in,
                              void* d_out, int out_size)
{
    const float4* x  = (const float4*)d_in[0];
    const int*    Xb = (const int*)d_in[1];
    const int*    Yb = (const int*)d_in[2];
    const int*    Wb = (const int*)d_in[3];
    const int*    Hb = (const int*)d_in[4];
    float4* out = (float4*)d_out;

    const int numTiles = (BB * CC * LL * LL) / (TILE_F4 * 4);  // 6144
    const int grid = 592;   // 4 persistent blocks per SM (smem-bound)
    masking_pipe<<<grid, THREADS>>>(x, Xb, Yb, Wb, Hb, out, numTiles);
}